// round 3
// baseline (speedup 1.0000x reference)
#include <cuda_runtime.h>
#include <cstdint>

#define B_ROWS 65536
#define HDIM 1024
#define NLAYERS 8
#define FIN 26
#define EPSV 1e-5f

__device__ float g_act[(size_t)B_ROWS * HDIM];
__device__ float g_norm[(size_t)B_ROWS * HDIM];
__device__ float g_xpad[(size_t)B_ROWS * 32];
__device__ float g_wpad[HDIM * 32];

__device__ __forceinline__ uint32_t smem_u32(const void* p) {
    uint32_t a;
    asm("{ .reg .u64 t; cvta.to.shared.u64 t, %1; cvt.u32.u64 %0, t; }" : "=r"(a) : "l"(p));
    return a;
}

// ---------------- tf32 mma.sync GEMM ----------------
// out[m0+.., n0+..] = relu(A @ W^T + bias). K = nk*32.
// CTA tile 128x128, 256 threads, 8 warps as 4(M) x 2(N); warp tile 32x64.
// SMEM: padded stride 36 floats -> conflict-free fragment loads.
#define KPAD 36
#define STAGE_F (2 * 128 * KPAD)          // floats per stage (A+B)
#define GEMM_SMEM (2 * STAGE_F * 4)       // bytes (2 stages)

__global__ void __launch_bounds__(256) gemm_kernel(
    const float* __restrict__ A, int lda,
    const float* __restrict__ W, int ldw,
    const float* __restrict__ bias, float* __restrict__ out, int nk)
{
    extern __shared__ float smem[];
    const int tid = threadIdx.x;
    const int wid = tid >> 5, lane = tid & 31;
    const int warpM = wid & 3, warpN = wid >> 2;
    const int m0 = blockIdx.y * 128, n0 = blockIdx.x * 128;
    const int gq = lane >> 2, tq = lane & 3;   // groupID, thread-in-group

    // cp.async setup: 4 segments of 16B per thread per tile (A and B)
    uint32_t sm_base = smem_u32(smem);

    auto load_stage = [&](int ki, int s) {
        uint32_t a_s = sm_base + (uint32_t)s * STAGE_F * 4;
        uint32_t b_s = a_s + 128 * KPAD * 4;
#pragma unroll
        for (int i = 0; i < 4; i++) {
            int seg = tid + i * 256;
            int row = seg >> 3, c4 = (seg & 7) * 4;
            const float* pa = A + (size_t)(m0 + row) * lda + ki * 32 + c4;
            const float* pb = W + (size_t)(n0 + row) * ldw + ki * 32 + c4;
            uint32_t off = (uint32_t)(row * KPAD + c4) * 4;
            asm volatile("cp.async.cg.shared.global [%0], [%1], 16;" :: "r"(a_s + off), "l"(pa));
            asm volatile("cp.async.cg.shared.global [%0], [%1], 16;" :: "r"(b_s + off), "l"(pb));
        }
        asm volatile("cp.async.commit_group;" ::: "memory");
    };

    float acc[2][8][4];
#pragma unroll
    for (int mi = 0; mi < 2; mi++)
#pragma unroll
        for (int j = 0; j < 8; j++)
#pragma unroll
            for (int q = 0; q < 4; q++) acc[mi][j][q] = 0.f;

    load_stage(0, 0);

    for (int ki = 0; ki < nk; ki++) {
        const int s = ki & 1;
        if (ki + 1 < nk) {
            load_stage(ki + 1, s ^ 1);
            asm volatile("cp.async.wait_group 1;" ::: "memory");
        } else {
            asm volatile("cp.async.wait_group 0;" ::: "memory");
        }
        __syncthreads();

        const float* As = smem + s * STAGE_F;
        const float* Bs = As + 128 * KPAD;
#pragma unroll
        for (int k0 = 0; k0 < 32; k0 += 8) {
            // B fragments: 8 n-tiles x 2 regs
            uint32_t bfr[8][2];
#pragma unroll
            for (int j = 0; j < 8; j++) {
                const int n = warpN * 64 + j * 8 + gq;
                bfr[j][0] = __float_as_uint(Bs[n * KPAD + k0 + tq]);
                bfr[j][1] = __float_as_uint(Bs[n * KPAD + k0 + 4 + tq]);
            }
            // A fragments: 2 m-tiles x 4 regs
            uint32_t afr[2][4];
#pragma unroll
            for (int mi = 0; mi < 2; mi++) {
                const int r = warpM * 32 + mi * 16 + gq;
                afr[mi][0] = __float_as_uint(As[r * KPAD + k0 + tq]);
                afr[mi][1] = __float_as_uint(As[(r + 8) * KPAD + k0 + tq]);
                afr[mi][2] = __float_as_uint(As[r * KPAD + k0 + 4 + tq]);
                afr[mi][3] = __float_as_uint(As[(r + 8) * KPAD + k0 + 4 + tq]);
            }
#pragma unroll
            for (int mi = 0; mi < 2; mi++)
#pragma unroll
                for (int j = 0; j < 8; j++)
                    asm volatile(
                        "mma.sync.aligned.m16n8k8.row.col.f32.tf32.tf32.f32 "
                        "{%0,%1,%2,%3}, {%4,%5,%6,%7}, {%8,%9}, {%0,%1,%2,%3};"
                        : "+f"(acc[mi][j][0]), "+f"(acc[mi][j][1]),
                          "+f"(acc[mi][j][2]), "+f"(acc[mi][j][3])
                        : "r"(afr[mi][0]), "r"(afr[mi][1]), "r"(afr[mi][2]), "r"(afr[mi][3]),
                          "r"(bfr[j][0]), "r"(bfr[j][1]));
        }
        __syncthreads();
    }

    // epilogue: bias + relu, float2 stores
#pragma unroll
    for (int mi = 0; mi < 2; mi++) {
        const int row = m0 + warpM * 32 + mi * 16 + gq;
#pragma unroll
        for (int j = 0; j < 8; j++) {
            const int col = n0 + warpN * 64 + j * 8 + tq * 2;
            const float b0 = __ldg(bias + col), b1 = __ldg(bias + col + 1);
            float2 v0, v1;
            v0.x = fmaxf(acc[mi][j][0] + b0, 0.f);
            v0.y = fmaxf(acc[mi][j][1] + b1, 0.f);
            v1.x = fmaxf(acc[mi][j][2] + b0, 0.f);
            v1.y = fmaxf(acc[mi][j][3] + b1, 0.f);
            *(float2*)(out + (size_t)row * HDIM + col) = v0;
            *(float2*)(out + (size_t)(row + 8) * HDIM + col) = v1;
        }
    }
}

// ---------------- stem LN(26) + pad to 32 ----------------
__global__ void stem_prep(const float* __restrict__ x, const float* __restrict__ g,
                          const float* __restrict__ bt)
{
    const int warp = (blockIdx.x * blockDim.x + threadIdx.x) >> 5;
    const int lane = threadIdx.x & 31;
    float v = (lane < FIN) ? x[(size_t)warp * FIN + lane] : 0.f;
    float s = v, sq = v * v;
#pragma unroll
    for (int o = 16; o > 0; o >>= 1) {
        s += __shfl_xor_sync(0xFFFFFFFFu, s, o);
        sq += __shfl_xor_sync(0xFFFFFFFFu, sq, o);
    }
    const float mean = s / (float)FIN;
    const float rstd = rsqrtf(sq / (float)FIN - mean * mean + EPSV);
    float ov = 0.f;
    if (lane < FIN) ov = (v - mean) * rstd * g[lane] + bt[lane];
    g_xpad[(size_t)warp * 32 + lane] = ov;
}

__global__ void stem_wpad(const float* __restrict__ w)
{
    const int i = blockIdx.x * blockDim.x + threadIdx.x;
    if (i < HDIM * 32) {
        const int j = i >> 5, k = i & 31;
        g_wpad[i] = (k < FIN) ? w[j * FIN + k] : 0.f;
    }
}

// ---------------- row stats helper ----------------
__device__ __forceinline__ void row_stats(float4 v, float* red0, float* red1, float* stats,
                                          int tid) {
    float s = v.x + v.y + v.z + v.w;
    float sq = v.x * v.x + v.y * v.y + v.z * v.z + v.w * v.w;
#pragma unroll
    for (int o = 16; o > 0; o >>= 1) {
        s += __shfl_xor_sync(0xFFFFFFFFu, s, o);
        sq += __shfl_xor_sync(0xFFFFFFFFu, sq, o);
    }
    const int w = tid >> 5, l = tid & 31;
    if (l == 0) { red0[w] = s; red1[w] = sq; }
    __syncthreads();
    if (tid < 32) {
        float a = (l < 8) ? red0[l] : 0.f;
        float b = (l < 8) ? red1[l] : 0.f;
#pragma unroll
        for (int o = 4; o > 0; o >>= 1) {
            a += __shfl_xor_sync(0xFFFFFFFFu, a, o);
            b += __shfl_xor_sync(0xFFFFFFFFu, b, o);
        }
        if (l == 0) {
            const float mean = a / (float)HDIM;
            stats[0] = mean;
            stats[1] = rsqrtf(b / (float)HDIM - mean * mean + EPSV);
        }
    }
    __syncthreads();
}

__global__ void ln_kernel(const float* __restrict__ g, const float* __restrict__ bb)
{
    __shared__ float red0[8], red1[8], stats[2];
    const int tid = threadIdx.x;
    const size_t rowoff = (size_t)blockIdx.x * HDIM;
    const float4 v = ((const float4*)(g_act + rowoff))[tid];
    row_stats(v, red0, red1, stats, tid);
    const float mean = stats[0], rstd = stats[1];
    const int c = tid * 4;
    const float4 gg = *(const float4*)(g + c);
    const float4 bv = *(const float4*)(bb + c);
    float4 o4;
    o4.x = (v.x - mean) * rstd * gg.x + bv.x;
    o4.y = (v.y - mean) * rstd * gg.y + bv.y;
    o4.z = (v.z - mean) * rstd * gg.z + bv.z;
    o4.w = (v.w - mean) * rstd * gg.w + bv.w;
    ((float4*)(g_norm + rowoff))[tid] = o4;
}

__global__ void head_kernel(const float* __restrict__ g, const float* __restrict__ bb,
                            const float* __restrict__ w, const float* __restrict__ b1,
                            float* __restrict__ out)
{
    __shared__ float red0[8], red1[8], stats[2];
    const int tid = threadIdx.x;
    const float4 v = ((const float4*)(g_act + (size_t)blockIdx.x * HDIM))[tid];
    row_stats(v, red0, red1, stats, tid);
    const float mean = stats[0], rstd = stats[1];
    const int c = tid * 4;
    const float4 gg = *(const float4*)(g + c);
    const float4 bv = *(const float4*)(bb + c);
    const float4 wv = *(const float4*)(w + c);
    float d = ((v.x - mean) * rstd * gg.x + bv.x) * wv.x +
              ((v.y - mean) * rstd * gg.y + bv.y) * wv.y +
              ((v.z - mean) * rstd * gg.z + bv.z) * wv.z +
              ((v.w - mean) * rstd * gg.w + bv.w) * wv.w;
#pragma unroll
    for (int o = 16; o > 0; o >>= 1)
        d += __shfl_xor_sync(0xFFFFFFFFu, d, o);
    __syncthreads();
    const int wI = tid >> 5, l = tid & 31;
    if (l == 0) red0[wI] = d;
    __syncthreads();
    if (tid == 0) {
        float a = red0[0] + red0[1] + red0[2] + red0[3] + red0[4] + red0[5] + red0[6] + red0[7];
        const float z = a + b1[0];
        out[blockIdx.x] = 1.f / (1.f + expf(-z));
    }
}

extern "C" void kernel_launch(void* const* d_in, const int* in_sizes, int n_in,
                              void* d_out, int out_size)
{
    const float* x          = (const float*)d_in[0];
    const float* st_gamma   = (const float*)d_in[1];
    const float* st_beta    = (const float*)d_in[2];
    const float* st_w       = (const float*)d_in[3];
    const float* st_b       = (const float*)d_in[4];
    const float* blk_gamma  = (const float*)d_in[5];
    const float* blk_beta   = (const float*)d_in[6];
    const float* blk_w      = (const float*)d_in[7];
    const float* blk_b      = (const float*)d_in[8];
    const float* last_gamma = (const float*)d_in[9];
    const float* last_beta  = (const float*)d_in[10];
    const float* last_w     = (const float*)d_in[11];
    const float* last_b     = (const float*)d_in[12];
    float* out = (float*)d_out;

    static bool attr_done = false;
    if (!attr_done) {
        cudaFuncSetAttribute(gemm_kernel, cudaFuncAttributeMaxDynamicSharedMemorySize, GEMM_SMEM);
        attr_done = true;
    }

    float* act;  cudaGetSymbolAddress((void**)&act, g_act);
    float* nrm;  cudaGetSymbolAddress((void**)&nrm, g_norm);
    float* xpad; cudaGetSymbolAddress((void**)&xpad, g_xpad);
    float* wpad; cudaGetSymbolAddress((void**)&wpad, g_wpad);

    stem_prep<<<B_ROWS / 8, 256>>>(x, st_gamma, st_beta);
    stem_wpad<<<(HDIM * 32) / 256, 256>>>(st_w);
    gemm_kernel<<<dim3(HDIM / 128, B_ROWS / 128), 256, GEMM_SMEM>>>(
        xpad, 32, wpad, 32, st_b, act, 1);

    for (int l = 0; l < NLAYERS; l++) {
        ln_kernel<<<B_ROWS, 256>>>(blk_gamma + l * HDIM, blk_beta + l * HDIM);
        gemm_kernel<<<dim3(HDIM / 128, B_ROWS / 128), 256, GEMM_SMEM>>>(
            nrm, HDIM, blk_w + (size_t)l * HDIM * HDIM, HDIM, blk_b + l * HDIM, act, HDIM / 32);
    }

    head_kernel<<<B_ROWS, 256>>>(last_gamma, last_beta, last_w, last_b, out);
}

// round 5
// speedup vs baseline: 1.7531x; 1.7531x over previous
#include <cuda_runtime.h>
#include <cuda_fp16.h>
#include <cstdint>

#define B_ROWS 65536
#define HDIM 1024
#define NLAYERS 8
#define FIN 26
#define EPSV 1e-5f

__device__ float  g_act[(size_t)B_ROWS * HDIM];
__device__ __half g_norm16[(size_t)B_ROWS * HDIM];
__device__ __half g_xpad16[(size_t)B_ROWS * 32];
__device__ __half g_w16[(size_t)NLAYERS * HDIM * HDIM];
__device__ __half g_wstem16[HDIM * 32];

__device__ __forceinline__ uint32_t smem_u32(const void* p) {
    uint32_t a;
    asm("{ .reg .u64 t; cvta.to.shared.u64 t, %1; cvt.u32.u64 %0, t; }" : "=r"(a) : "l"(p));
    return a;
}

// ---------------- fp16 mma.sync GEMM ----------------
// out[m,n] = relu(A @ W^T + bias). A:[.,lda] half, W:[.,ldw] half. K = nk*32.
// CTA tile 256x128, 256 thr, 8 warps = 4(M) x 2(N), warp tile 64x64.
// SMEM row stride 40 halves (80B): conflict-free ldmatrix (banks r*20 mod 32 distinct).
#define KP 40
#define A_H (256 * KP)              // halves
#define B_H (128 * KP)
#define STAGE_B ((A_H + B_H) * 2)   // bytes = 30720
#define GEMM_SMEM (2 * STAGE_B)

__global__ void __launch_bounds__(256) gemm16(
    const __half* __restrict__ A, int lda,
    const __half* __restrict__ W, int ldw,
    const float* __restrict__ bias, float* __restrict__ out, int nk)
{
    extern __shared__ __half smem[];
    const int tid = threadIdx.x;
    const int wid = tid >> 5, lane = tid & 31;
    const int warpM = wid & 3, warpN = wid >> 2;
    const int m0 = blockIdx.y * 256, n0 = blockIdx.x * 128;
    const uint32_t base = smem_u32(smem);

    auto load_stage = [&](int ki, int s) {
        const uint32_t st = base + (uint32_t)s * STAGE_B;
#pragma unroll
        for (int i = 0; i < 4; i++) {       // A: 256 rows x 64B
            const int seg = tid + i * 256;
            const int row = seg >> 2, c16 = seg & 3;
            const __half* src = A + (size_t)(m0 + row) * lda + ki * 32 + c16 * 8;
            asm volatile("cp.async.cg.shared.global [%0], [%1], 16;"
                         :: "r"(st + row * 80 + c16 * 16), "l"(src));
        }
#pragma unroll
        for (int i = 0; i < 2; i++) {       // B: 128 rows x 64B
            const int seg = tid + i * 256;
            const int row = seg >> 2, c16 = seg & 3;
            const __half* src = W + (size_t)(n0 + row) * ldw + ki * 32 + c16 * 8;
            asm volatile("cp.async.cg.shared.global [%0], [%1], 16;"
                         :: "r"(st + A_H * 2 + row * 80 + c16 * 16), "l"(src));
        }
        asm volatile("cp.async.commit_group;" ::: "memory");
    };

    // ldmatrix per-lane offsets
    const int aRow = warpM * 64 + (lane & 7) + ((lane >> 3) & 1) * 8;
    const int aK   = (lane >> 4) * 8;
    const int bN   = warpN * 64 + (lane & 7) + (lane >> 4) * 8;
    const int bK   = ((lane >> 3) & 1) * 8;

    float acc[4][8][4];
#pragma unroll
    for (int mi = 0; mi < 4; mi++)
#pragma unroll
        for (int nj = 0; nj < 8; nj++)
#pragma unroll
            for (int q = 0; q < 4; q++) acc[mi][nj][q] = 0.f;

    load_stage(0, 0);

    for (int ki = 0; ki < nk; ki++) {
        const int s = ki & 1;
        if (ki + 1 < nk) {
            load_stage(ki + 1, s ^ 1);
            asm volatile("cp.async.wait_group 1;" ::: "memory");
        } else {
            asm volatile("cp.async.wait_group 0;" ::: "memory");
        }
        __syncthreads();

        const uint32_t As = base + (uint32_t)s * STAGE_B;
        const uint32_t Bs = As + A_H * 2;
#pragma unroll
        for (int k0 = 0; k0 < 32; k0 += 16) {
            uint32_t a[4][4], b[4][4];
#pragma unroll
            for (int mi = 0; mi < 4; mi++) {
                const uint32_t ad = As + (uint32_t)((aRow + mi * 16) * KP + k0 + aK) * 2;
                asm volatile("ldmatrix.sync.aligned.m8n8.x4.shared.b16 {%0,%1,%2,%3}, [%4];"
                             : "=r"(a[mi][0]), "=r"(a[mi][1]), "=r"(a[mi][2]), "=r"(a[mi][3])
                             : "r"(ad));
            }
#pragma unroll
            for (int p = 0; p < 4; p++) {
                const uint32_t bd = Bs + (uint32_t)((bN + p * 16) * KP + k0 + bK) * 2;
                asm volatile("ldmatrix.sync.aligned.m8n8.x4.shared.b16 {%0,%1,%2,%3}, [%4];"
                             : "=r"(b[p][0]), "=r"(b[p][1]), "=r"(b[p][2]), "=r"(b[p][3])
                             : "r"(bd));
            }
#pragma unroll
            for (int mi = 0; mi < 4; mi++)
#pragma unroll
                for (int nj = 0; nj < 8; nj++) {
                    const uint32_t b0 = b[nj >> 1][(nj & 1) * 2];
                    const uint32_t b1 = b[nj >> 1][(nj & 1) * 2 + 1];
                    asm volatile(
                        "mma.sync.aligned.m16n8k16.row.col.f32.f16.f16.f32 "
                        "{%0,%1,%2,%3}, {%4,%5,%6,%7}, {%8,%9}, {%0,%1,%2,%3};"
                        : "+f"(acc[mi][nj][0]), "+f"(acc[mi][nj][1]),
                          "+f"(acc[mi][nj][2]), "+f"(acc[mi][nj][3])
                        : "r"(a[mi][0]), "r"(a[mi][1]), "r"(a[mi][2]), "r"(a[mi][3]),
                          "r"(b0), "r"(b1));
                }
        }
        __syncthreads();
    }

#pragma unroll
    for (int mi = 0; mi < 4; mi++) {
        const int row = m0 + warpM * 64 + mi * 16 + (lane >> 2);
#pragma unroll
        for (int nj = 0; nj < 8; nj++) {
            const int col = n0 + warpN * 64 + nj * 8 + (lane & 3) * 2;
            const float b0 = __ldg(bias + col), b1 = __ldg(bias + col + 1);
            float2 v0, v1;
            v0.x = fmaxf(acc[mi][nj][0] + b0, 0.f);
            v0.y = fmaxf(acc[mi][nj][1] + b1, 0.f);
            v1.x = fmaxf(acc[mi][nj][2] + b0, 0.f);
            v1.y = fmaxf(acc[mi][nj][3] + b1, 0.f);
            *(float2*)(out + (size_t)row * HDIM + col) = v0;
            *(float2*)(out + (size_t)(row + 8) * HDIM + col) = v1;
        }
    }
}

// ---------------- weight conversion ----------------
__global__ void wconv(const float* __restrict__ w) {
    const int i = blockIdx.x * blockDim.x + threadIdx.x;
    g_w16[i] = __float2half_rn(w[i]);
}
__global__ void stem_wpad(const float* __restrict__ w) {
    const int i = blockIdx.x * blockDim.x + threadIdx.x;
    if (i < HDIM * 32) {
        const int j = i >> 5, k = i & 31;
        g_wstem16[i] = __float2half_rn((k < FIN) ? w[j * FIN + k] : 0.f);
    }
}

// ---------------- stem LN(26) + pad to 32, fp16 out ----------------
__global__ void stem_prep(const float* __restrict__ x, const float* __restrict__ g,
                          const float* __restrict__ bt)
{
    const int warp = (blockIdx.x * blockDim.x + threadIdx.x) >> 5;
    const int lane = threadIdx.x & 31;
    float v = (lane < FIN) ? x[(size_t)warp * FIN + lane] : 0.f;
    float s = v, sq = v * v;
#pragma unroll
    for (int o = 16; o > 0; o >>= 1) {
        s += __shfl_xor_sync(0xFFFFFFFFu, s, o);
        sq += __shfl_xor_sync(0xFFFFFFFFu, sq, o);
    }
    const float mean = s / (float)FIN;
    const float rstd = rsqrtf(sq / (float)FIN - mean * mean + EPSV);
    float ov = 0.f;
    if (lane < FIN) ov = (v - mean) * rstd * g[lane] + bt[lane];
    g_xpad16[(size_t)warp * 32 + lane] = __float2half_rn(ov);
}

__device__ __forceinline__ void row_stats(float4 v, float* red0, float* red1, float* stats,
                                          int tid) {
    float s = v.x + v.y + v.z + v.w;
    float sq = v.x * v.x + v.y * v.y + v.z * v.z + v.w * v.w;
#pragma unroll
    for (int o = 16; o > 0; o >>= 1) {
        s += __shfl_xor_sync(0xFFFFFFFFu, s, o);
        sq += __shfl_xor_sync(0xFFFFFFFFu, sq, o);
    }
    const int w = tid >> 5, l = tid & 31;
    if (l == 0) { red0[w] = s; red1[w] = sq; }
    __syncthreads();
    if (tid < 32) {
        float a = (l < 8) ? red0[l] : 0.f;
        float b = (l < 8) ? red1[l] : 0.f;
#pragma unroll
        for (int o = 4; o > 0; o >>= 1) {
            a += __shfl_xor_sync(0xFFFFFFFFu, a, o);
            b += __shfl_xor_sync(0xFFFFFFFFu, b, o);
        }
        if (l == 0) {
            const float mean = a / (float)HDIM;
            stats[0] = mean;
            stats[1] = rsqrtf(b / (float)HDIM - mean * mean + EPSV);
        }
    }
    __syncthreads();
}

// LN: read fp32 g_act, write fp16 g_norm16
__global__ void ln16(const float* __restrict__ g, const float* __restrict__ bb)
{
    __shared__ float red0[8], red1[8], stats[2];
    const int tid = threadIdx.x;
    const size_t rowoff = (size_t)blockIdx.x * HDIM;
    const float4 v = ((const float4*)(g_act + rowoff))[tid];
    row_stats(v, red0, red1, stats, tid);
    const float mean = stats[0], rstd = stats[1];
    const int c = tid * 4;
    const float4 gg = *(const float4*)(g + c);
    const float4 bv = *(const float4*)(bb + c);
    __half2 h01 = __floats2half2_rn((v.x - mean) * rstd * gg.x + bv.x,
                                    (v.y - mean) * rstd * gg.y + bv.y);
    __half2 h23 = __floats2half2_rn((v.z - mean) * rstd * gg.z + bv.z,
                                    (v.w - mean) * rstd * gg.w + bv.w);
    uint2 o;
    o.x = *(uint32_t*)&h01;
    o.y = *(uint32_t*)&h23;
    ((uint2*)(g_norm16 + rowoff))[tid] = o;
}

__global__ void head_kernel(const float* __restrict__ g, const float* __restrict__ bb,
                            const float* __restrict__ w, const float* __restrict__ b1,
                            float* __restrict__ out)
{
    __shared__ float red0[8], red1[8], stats[2];
    const int tid = threadIdx.x;
    const float4 v = ((const float4*)(g_act + (size_t)blockIdx.x * HDIM))[tid];
    row_stats(v, red0, red1, stats, tid);
    const float mean = stats[0], rstd = stats[1];
    const int c = tid * 4;
    const float4 gg = *(const float4*)(g + c);
    const float4 bv = *(const float4*)(bb + c);
    const float4 wv = *(const float4*)(w + c);
    float d = ((v.x - mean) * rstd * gg.x + bv.x) * wv.x +
              ((v.y - mean) * rstd * gg.y + bv.y) * wv.y +
              ((v.z - mean) * rstd * gg.z + bv.z) * wv.z +
              ((v.w - mean) * rstd * gg.w + bv.w) * wv.w;
#pragma unroll
    for (int o = 16; o > 0; o >>= 1)
        d += __shfl_xor_sync(0xFFFFFFFFu, d, o);
    __syncthreads();
    const int wI = tid >> 5, l = tid & 31;
    if (l == 0) red0[wI] = d;
    __syncthreads();
    if (tid == 0) {
        float a = red0[0] + red0[1] + red0[2] + red0[3] + red0[4] + red0[5] + red0[6] + red0[7];
        out[blockIdx.x] = 1.f / (1.f + expf(-(a + b1[0])));
    }
}

extern "C" void kernel_launch(void* const* d_in, const int* in_sizes, int n_in,
                              void* d_out, int out_size)
{
    const float* x          = (const float*)d_in[0];
    const float* st_gamma   = (const float*)d_in[1];
    const float* st_beta    = (const float*)d_in[2];
    const float* st_w       = (const float*)d_in[3];
    const float* st_b       = (const float*)d_in[4];
    const float* blk_gamma  = (const float*)d_in[5];
    const float* blk_beta   = (const float*)d_in[6];
    const float* blk_w      = (const float*)d_in[7];
    const float* blk_b      = (const float*)d_in[8];
    const float* last_gamma = (const float*)d_in[9];
    const float* last_beta  = (const float*)d_in[10];
    const float* last_w     = (const float*)d_in[11];
    const float* last_b     = (const float*)d_in[12];
    float* out = (float*)d_out;

    static bool attr_done = false;
    if (!attr_done) {
        cudaFuncSetAttribute(gemm16, cudaFuncAttributeMaxDynamicSharedMemorySize, GEMM_SMEM);
        attr_done = true;
    }

    float* act;      cudaGetSymbolAddress((void**)&act, g_act);
    __half* nrm;     cudaGetSymbolAddress((void**)&nrm, g_norm16);
    __half* xpad;    cudaGetSymbolAddress((void**)&xpad, g_xpad16);
    __half* w16;     cudaGetSymbolAddress((void**)&w16, g_w16);
    __half* wstem;   cudaGetSymbolAddress((void**)&wstem, g_wstem16);

    wconv<<<(NLAYERS * HDIM * HDIM) / 256, 256>>>(blk_w);
    stem_wpad<<<(HDIM * 32) / 256, 256>>>(st_w);
    stem_prep<<<B_ROWS / 8, 256>>>(x, st_gamma, st_beta);

    gemm16<<<dim3(HDIM / 128, B_ROWS / 256), 256, GEMM_SMEM>>>(
        xpad, 32, wstem, 32, st_b, act, 1);

    for (int l = 0; l < NLAYERS; l++) {
        ln16<<<B_ROWS, 256>>>(blk_gamma + l * HDIM, blk_beta + l * HDIM);
        gemm16<<<dim3(HDIM / 128, B_ROWS / 256), 256, GEMM_SMEM>>>(
            nrm, HDIM, w16 + (size_t)l * HDIM * HDIM, HDIM, blk_b + l * HDIM, act, HDIM / 32);
    }

    head_kernel<<<B_ROWS, 256>>>(last_gamma, last_beta, last_w, last_b, out);
}

// round 6
// speedup vs baseline: 1.9139x; 1.0917x over previous
#include <cuda_runtime.h>
#include <cuda_fp16.h>
#include <cstdint>

#define B_ROWS 65536
#define HDIM 1024
#define NLAYERS 8
#define FIN 26
#define EPSV 1e-5f

__device__ float  g_act[(size_t)B_ROWS * HDIM];
__device__ __half g_norm16[(size_t)B_ROWS * HDIM];
__device__ __half g_xpad16[(size_t)B_ROWS * 32];
__device__ __half g_w16[(size_t)NLAYERS * HDIM * HDIM];
__device__ __half g_wstem16[HDIM * 32];

__device__ __forceinline__ uint32_t smem_u32(const void* p) {
    uint32_t a;
    asm("{ .reg .u64 t; cvta.to.shared.u64 t, %1; cvt.u32.u64 %0, t; }" : "=r"(a) : "l"(p));
    return a;
}

// ---------------- fp16 mma.sync GEMM ----------------
// out = relu(A @ W^T + bias). CTA tile 128x128, 256 thr, warps 2(M) x 4(N),
// warp tile 64x32. 4-stage cp.async pipeline. SMEM row stride 40 halves.
#define KP 40
#define STAGES 4
#define STAGE_B ((128 + 128) * KP * 2)     // 20480 bytes
#define GEMM_SMEM (STAGES * STAGE_B)       // 81920

__global__ void __launch_bounds__(256, 2) gemm16(
    const __half* __restrict__ A, int lda,
    const __half* __restrict__ W, int ldw,
    const float* __restrict__ bias, float* __restrict__ out, int nk)
{
    extern __shared__ __half smem[];
    const int tid = threadIdx.x;
    const int wid = tid >> 5, lane = tid & 31;
    const int warpM = wid & 1, warpN = wid >> 1;
    const int m0 = blockIdx.y * 128, n0 = blockIdx.x * 128;
    const uint32_t base = smem_u32(smem);

    auto load_stage = [&](int ki, int s) {
        const uint32_t st = base + (uint32_t)s * STAGE_B;
#pragma unroll
        for (int i = 0; i < 2; i++) {       // A: 128 rows x 64B
            const int seg = tid + i * 256;
            const int row = seg >> 2, c16 = seg & 3;
            const __half* src = A + (size_t)(m0 + row) * lda + ki * 32 + c16 * 8;
            asm volatile("cp.async.cg.shared.global [%0], [%1], 16;"
                         :: "r"(st + row * 80 + c16 * 16), "l"(src));
        }
#pragma unroll
        for (int i = 0; i < 2; i++) {       // B: 128 rows x 64B
            const int seg = tid + i * 256;
            const int row = seg >> 2, c16 = seg & 3;
            const __half* src = W + (size_t)(n0 + row) * ldw + ki * 32 + c16 * 8;
            asm volatile("cp.async.cg.shared.global [%0], [%1], 16;"
                         :: "r"(st + 128 * 80 + row * 80 + c16 * 16), "l"(src));
        }
        asm volatile("cp.async.commit_group;" ::: "memory");
    };

    // ldmatrix per-lane offsets
    const int aRow = warpM * 64 + (lane & 7) + ((lane >> 3) & 1) * 8;
    const int aK   = (lane >> 4) * 8;
    const int bN   = warpN * 32 + (lane & 7) + (lane >> 4) * 8;
    const int bK   = ((lane >> 3) & 1) * 8;

    float acc[4][4][4];
#pragma unroll
    for (int mi = 0; mi < 4; mi++)
#pragma unroll
        for (int nj = 0; nj < 4; nj++)
#pragma unroll
            for (int q = 0; q < 4; q++) acc[mi][nj][q] = 0.f;

#pragma unroll
    for (int p = 0; p < STAGES - 1; p++)
        if (p < nk) load_stage(p, p);

    for (int ki = 0; ki < nk; ki++) {
        const int s = ki & (STAGES - 1);
        if (ki + STAGES - 1 < nk) {
            load_stage(ki + STAGES - 1, (ki + STAGES - 1) & (STAGES - 1));
            asm volatile("cp.async.wait_group 2;" ::: "memory");
        } else {
            asm volatile("cp.async.wait_group 0;" ::: "memory");
        }
        __syncthreads();

        const uint32_t As = base + (uint32_t)s * STAGE_B;
        const uint32_t Bs = As + 128 * 80;
#pragma unroll
        for (int k0 = 0; k0 < 32; k0 += 16) {
            uint32_t a[4][4], b[2][4];
#pragma unroll
            for (int mi = 0; mi < 4; mi++) {
                const uint32_t ad = As + (uint32_t)((aRow + mi * 16) * KP + k0 + aK) * 2;
                asm volatile("ldmatrix.sync.aligned.m8n8.x4.shared.b16 {%0,%1,%2,%3}, [%4];"
                             : "=r"(a[mi][0]), "=r"(a[mi][1]), "=r"(a[mi][2]), "=r"(a[mi][3])
                             : "r"(ad));
            }
#pragma unroll
            for (int p = 0; p < 2; p++) {
                const uint32_t bd = Bs + (uint32_t)((bN + p * 16) * KP + k0 + bK) * 2;
                asm volatile("ldmatrix.sync.aligned.m8n8.x4.shared.b16 {%0,%1,%2,%3}, [%4];"
                             : "=r"(b[p][0]), "=r"(b[p][1]), "=r"(b[p][2]), "=r"(b[p][3])
                             : "r"(bd));
            }
#pragma unroll
            for (int mi = 0; mi < 4; mi++)
#pragma unroll
                for (int nj = 0; nj < 4; nj++) {
                    const uint32_t b0 = b[nj >> 1][(nj & 1) * 2];
                    const uint32_t b1 = b[nj >> 1][(nj & 1) * 2 + 1];
                    asm volatile(
                        "mma.sync.aligned.m16n8k16.row.col.f32.f16.f16.f32 "
                        "{%0,%1,%2,%3}, {%4,%5,%6,%7}, {%8,%9}, {%0,%1,%2,%3};"
                        : "+f"(acc[mi][nj][0]), "+f"(acc[mi][nj][1]),
                          "+f"(acc[mi][nj][2]), "+f"(acc[mi][nj][3])
                        : "r"(a[mi][0]), "r"(a[mi][1]), "r"(a[mi][2]), "r"(a[mi][3]),
                          "r"(b0), "r"(b1));
                }
        }
        __syncthreads();
    }

#pragma unroll
    for (int mi = 0; mi < 4; mi++) {
        const int row = m0 + warpM * 64 + mi * 16 + (lane >> 2);
#pragma unroll
        for (int nj = 0; nj < 4; nj++) {
            const int col = n0 + warpN * 32 + nj * 8 + (lane & 3) * 2;
            const float b0 = __ldg(bias + col), b1 = __ldg(bias + col + 1);
            float2 v0, v1;
            v0.x = fmaxf(acc[mi][nj][0] + b0, 0.f);
            v0.y = fmaxf(acc[mi][nj][1] + b1, 0.f);
            v1.x = fmaxf(acc[mi][nj][2] + b0, 0.f);
            v1.y = fmaxf(acc[mi][nj][3] + b1, 0.f);
            *(float2*)(out + (size_t)row * HDIM + col) = v0;
            *(float2*)(out + (size_t)(row + 8) * HDIM + col) = v1;
        }
    }
}

// ---------------- weight conversion ----------------
__global__ void wconv(const float* __restrict__ w) {
    const int i = blockIdx.x * blockDim.x + threadIdx.x;
    g_w16[i] = __float2half_rn(w[i]);
}
__global__ void stem_wpad(const float* __restrict__ w) {
    const int i = blockIdx.x * blockDim.x + threadIdx.x;
    if (i < HDIM * 32) {
        const int j = i >> 5, k = i & 31;
        g_wstem16[i] = __float2half_rn((k < FIN) ? w[j * FIN + k] : 0.f);
    }
}

// ---------------- stem LN(26) + pad to 32, fp16 out ----------------
__global__ void stem_prep(const float* __restrict__ x, const float* __restrict__ g,
                          const float* __restrict__ bt)
{
    const int warp = (blockIdx.x * blockDim.x + threadIdx.x) >> 5;
    const int lane = threadIdx.x & 31;
    float v = (lane < FIN) ? x[(size_t)warp * FIN + lane] : 0.f;
    float s = v, sq = v * v;
#pragma unroll
    for (int o = 16; o > 0; o >>= 1) {
        s += __shfl_xor_sync(0xFFFFFFFFu, s, o);
        sq += __shfl_xor_sync(0xFFFFFFFFu, sq, o);
    }
    const float mean = s / (float)FIN;
    const float rstd = rsqrtf(sq / (float)FIN - mean * mean + EPSV);
    float ov = 0.f;
    if (lane < FIN) ov = (v - mean) * rstd * g[lane] + bt[lane];
    g_xpad16[(size_t)warp * 32 + lane] = __float2half_rn(ov);
}

__device__ __forceinline__ void row_stats(float4 v, float* red0, float* red1, float* stats,
                                          int tid) {
    float s = v.x + v.y + v.z + v.w;
    float sq = v.x * v.x + v.y * v.y + v.z * v.z + v.w * v.w;
#pragma unroll
    for (int o = 16; o > 0; o >>= 1) {
        s += __shfl_xor_sync(0xFFFFFFFFu, s, o);
        sq += __shfl_xor_sync(0xFFFFFFFFu, sq, o);
    }
    const int w = tid >> 5, l = tid & 31;
    if (l == 0) { red0[w] = s; red1[w] = sq; }
    __syncthreads();
    if (tid < 32) {
        float a = (l < 8) ? red0[l] : 0.f;
        float b = (l < 8) ? red1[l] : 0.f;
#pragma unroll
        for (int o = 4; o > 0; o >>= 1) {
            a += __shfl_xor_sync(0xFFFFFFFFu, a, o);
            b += __shfl_xor_sync(0xFFFFFFFFu, b, o);
        }
        if (l == 0) {
            const float mean = a / (float)HDIM;
            stats[0] = mean;
            stats[1] = rsqrtf(b / (float)HDIM - mean * mean + EPSV);
        }
    }
    __syncthreads();
}

// LN: read fp32 g_act, write fp16 g_norm16
__global__ void ln16(const float* __restrict__ g, const float* __restrict__ bb)
{
    __shared__ float red0[8], red1[8], stats[2];
    const int tid = threadIdx.x;
    const size_t rowoff = (size_t)blockIdx.x * HDIM;
    const float4 v = ((const float4*)(g_act + rowoff))[tid];
    row_stats(v, red0, red1, stats, tid);
    const float mean = stats[0], rstd = stats[1];
    const int c = tid * 4;
    const float4 gg = *(const float4*)(g + c);
    const float4 bv = *(const float4*)(bb + c);
    __half2 h01 = __floats2half2_rn((v.x - mean) * rstd * gg.x + bv.x,
                                    (v.y - mean) * rstd * gg.y + bv.y);
    __half2 h23 = __floats2half2_rn((v.z - mean) * rstd * gg.z + bv.z,
                                    (v.w - mean) * rstd * gg.w + bv.w);
    uint2 o;
    o.x = *(uint32_t*)&h01;
    o.y = *(uint32_t*)&h23;
    ((uint2*)(g_norm16 + rowoff))[tid] = o;
}

__global__ void head_kernel(const float* __restrict__ g, const float* __restrict__ bb,
                            const float* __restrict__ w, const float* __restrict__ b1,
                            float* __restrict__ out)
{
    __shared__ float red0[8], red1[8], stats[2];
    const int tid = threadIdx.x;
    const float4 v = ((const float4*)(g_act + (size_t)blockIdx.x * HDIM))[tid];
    row_stats(v, red0, red1, stats, tid);
    const float mean = stats[0], rstd = stats[1];
    const int c = tid * 4;
    const float4 gg = *(const float4*)(g + c);
    const float4 bv = *(const float4*)(bb + c);
    const float4 wv = *(const float4*)(w + c);
    float d = ((v.x - mean) * rstd * gg.x + bv.x) * wv.x +
              ((v.y - mean) * rstd * gg.y + bv.y) * wv.y +
              ((v.z - mean) * rstd * gg.z + bv.z) * wv.z +
              ((v.w - mean) * rstd * gg.w + bv.w) * wv.w;
#pragma unroll
    for (int o = 16; o > 0; o >>= 1)
        d += __shfl_xor_sync(0xFFFFFFFFu, d, o);
    __syncthreads();
    const int wI = tid >> 5, l = tid & 31;
    if (l == 0) red0[wI] = d;
    __syncthreads();
    if (tid == 0) {
        float a = red0[0] + red0[1] + red0[2] + red0[3] + red0[4] + red0[5] + red0[6] + red0[7];
        out[blockIdx.x] = 1.f / (1.f + expf(-(a + b1[0])));
    }
}

extern "C" void kernel_launch(void* const* d_in, const int* in_sizes, int n_in,
                              void* d_out, int out_size)
{
    const float* x          = (const float*)d_in[0];
    const float* st_gamma   = (const float*)d_in[1];
    const float* st_beta    = (const float*)d_in[2];
    const float* st_w       = (const float*)d_in[3];
    const float* st_b       = (const float*)d_in[4];
    const float* blk_gamma  = (const float*)d_in[5];
    const float* blk_beta   = (const float*)d_in[6];
    const float* blk_w      = (const float*)d_in[7];
    const float* blk_b      = (const float*)d_in[8];
    const float* last_gamma = (const float*)d_in[9];
    const float* last_beta  = (const float*)d_in[10];
    const float* last_w     = (const float*)d_in[11];
    const float* last_b     = (const float*)d_in[12];
    float* out = (float*)d_out;

    static bool attr_done = false;
    if (!attr_done) {
        cudaFuncSetAttribute(gemm16, cudaFuncAttributeMaxDynamicSharedMemorySize, GEMM_SMEM);
        attr_done = true;
    }

    float* act;      cudaGetSymbolAddress((void**)&act, g_act);
    __half* nrm;     cudaGetSymbolAddress((void**)&nrm, g_norm16);
    __half* xpad;    cudaGetSymbolAddress((void**)&xpad, g_xpad16);
    __half* w16;     cudaGetSymbolAddress((void**)&w16, g_w16);
    __half* wstem;   cudaGetSymbolAddress((void**)&wstem, g_wstem16);

    wconv<<<(NLAYERS * HDIM * HDIM) / 256, 256>>>(blk_w);
    stem_wpad<<<(HDIM * 32) / 256, 256>>>(st_w);
    stem_prep<<<B_ROWS / 8, 256>>>(x, st_gamma, st_beta);

    gemm16<<<dim3(HDIM / 128, B_ROWS / 128), 256, GEMM_SMEM>>>(
        xpad, 32, wstem, 32, st_b, act, 1);

    for (int l = 0; l < NLAYERS; l++) {
        ln16<<<B_ROWS, 256>>>(blk_gamma + l * HDIM, blk_beta + l * HDIM);
        gemm16<<<dim3(HDIM / 128, B_ROWS / 128), 256, GEMM_SMEM>>>(
            nrm, HDIM, w16 + (size_t)l * HDIM * HDIM, HDIM, blk_b + l * HDIM, act, HDIM / 32);
    }

    head_kernel<<<B_ROWS, 256>>>(last_gamma, last_beta, last_w, last_b, out);
}

// round 7
// speedup vs baseline: 2.0732x; 1.0832x over previous
#include <cuda_runtime.h>
#include <cuda_fp16.h>
#include <cstdint>

#define B_ROWS 65536
#define HDIM 1024
#define NLAYERS 8
#define FIN 26
#define EPSV 1e-5f

__device__ __half g_a0[(size_t)B_ROWS * HDIM];
__device__ __half g_a1[(size_t)B_ROWS * HDIM];
__device__ __half g_xpad16[(size_t)B_ROWS * 32];
__device__ __half g_w16[(size_t)NLAYERS * HDIM * HDIM];   // gamma ⊙ W, fp16
__device__ __half g_wstem16[HDIM * 32];
__device__ float2 g_part[(size_t)B_ROWS * 8];   // per-row, per-nCTA (sum, sumsq)
__device__ float2 g_stats[B_ROWS];              // (rstd, -rstd*mean)
__device__ float  g_c1[NLAYERS * HDIM];         // sum_k gamma_k W[n,k]
__device__ float  g_c2[NLAYERS * HDIM];         // sum_k beta_k W[n,k] + bias[n]

__device__ __forceinline__ uint32_t smem_u32(const void* p) {
    uint32_t a;
    asm("{ .reg .u64 t; cvta.to.shared.u64 t, %1; cvt.u32.u64 %0, t; }" : "=r"(a) : "l"(p));
    return a;
}

// ---------------- fp16 mma.sync GEMM with fused-LN epilogue ----------------
// fused=1: val = r*dot + rm*c1[n] + c2[n];  fused=0: val = dot + c2[n]
// Always: relu, fp16 store, per-row (sum,sumsq) partials -> part[row*8 + blockIdx.x]
#define KP 40
#define STAGES 4
#define STAGE_B ((128 + 128) * KP * 2)     // 20480 bytes
#define GEMM_SMEM (STAGES * STAGE_B)       // 81920

__global__ void __launch_bounds__(256, 2) gemm16(
    const __half* __restrict__ A, int lda,
    const __half* __restrict__ W, int ldw,
    const float2* __restrict__ stats,
    const float* __restrict__ c1, const float* __restrict__ c2,
    __half* __restrict__ out16, float2* __restrict__ part,
    int nk, int fused)
{
    extern __shared__ __half smem[];
    const int tid = threadIdx.x;
    const int wid = tid >> 5, lane = tid & 31;
    const int warpM = wid & 1, warpN = wid >> 1;
    const int m0 = blockIdx.y * 128, n0 = blockIdx.x * 128;
    const uint32_t base = smem_u32(smem);

    auto load_stage = [&](int ki, int s) {
        const uint32_t st = base + (uint32_t)s * STAGE_B;
#pragma unroll
        for (int i = 0; i < 2; i++) {
            const int seg = tid + i * 256;
            const int row = seg >> 2, c16 = seg & 3;
            const __half* src = A + (size_t)(m0 + row) * lda + ki * 32 + c16 * 8;
            asm volatile("cp.async.cg.shared.global [%0], [%1], 16;"
                         :: "r"(st + row * 80 + c16 * 16), "l"(src));
        }
#pragma unroll
        for (int i = 0; i < 2; i++) {
            const int seg = tid + i * 256;
            const int row = seg >> 2, c16 = seg & 3;
            const __half* src = W + (size_t)(n0 + row) * ldw + ki * 32 + c16 * 8;
            asm volatile("cp.async.cg.shared.global [%0], [%1], 16;"
                         :: "r"(st + 128 * 80 + row * 80 + c16 * 16), "l"(src));
        }
        asm volatile("cp.async.commit_group;" ::: "memory");
    };

    const int aRow = warpM * 64 + (lane & 7) + ((lane >> 3) & 1) * 8;
    const int aK   = (lane >> 4) * 8;
    const int bN   = warpN * 32 + (lane & 7) + (lane >> 4) * 8;
    const int bK   = ((lane >> 3) & 1) * 8;

    float acc[4][4][4];
#pragma unroll
    for (int mi = 0; mi < 4; mi++)
#pragma unroll
        for (int nj = 0; nj < 4; nj++)
#pragma unroll
            for (int q = 0; q < 4; q++) acc[mi][nj][q] = 0.f;

#pragma unroll
    for (int p = 0; p < STAGES - 1; p++)
        if (p < nk) load_stage(p, p);

    for (int ki = 0; ki < nk; ki++) {
        const int s = ki & (STAGES - 1);
        if (ki + STAGES - 1 < nk) {
            load_stage(ki + STAGES - 1, (ki + STAGES - 1) & (STAGES - 1));
            asm volatile("cp.async.wait_group 2;" ::: "memory");
        } else {
            asm volatile("cp.async.wait_group 0;" ::: "memory");
        }
        __syncthreads();

        const uint32_t As = base + (uint32_t)s * STAGE_B;
        const uint32_t Bs = As + 128 * 80;
#pragma unroll
        for (int k0 = 0; k0 < 32; k0 += 16) {
            uint32_t a[4][4], b[2][4];
#pragma unroll
            for (int mi = 0; mi < 4; mi++) {
                const uint32_t ad = As + (uint32_t)((aRow + mi * 16) * KP + k0 + aK) * 2;
                asm volatile("ldmatrix.sync.aligned.m8n8.x4.shared.b16 {%0,%1,%2,%3}, [%4];"
                             : "=r"(a[mi][0]), "=r"(a[mi][1]), "=r"(a[mi][2]), "=r"(a[mi][3])
                             : "r"(ad));
            }
#pragma unroll
            for (int p = 0; p < 2; p++) {
                const uint32_t bd = Bs + (uint32_t)((bN + p * 16) * KP + k0 + bK) * 2;
                asm volatile("ldmatrix.sync.aligned.m8n8.x4.shared.b16 {%0,%1,%2,%3}, [%4];"
                             : "=r"(b[p][0]), "=r"(b[p][1]), "=r"(b[p][2]), "=r"(b[p][3])
                             : "r"(bd));
            }
#pragma unroll
            for (int mi = 0; mi < 4; mi++)
#pragma unroll
                for (int nj = 0; nj < 4; nj++) {
                    const uint32_t b0 = b[nj >> 1][(nj & 1) * 2];
                    const uint32_t b1 = b[nj >> 1][(nj & 1) * 2 + 1];
                    asm volatile(
                        "mma.sync.aligned.m16n8k16.row.col.f32.f16.f16.f32 "
                        "{%0,%1,%2,%3}, {%4,%5,%6,%7}, {%8,%9}, {%0,%1,%2,%3};"
                        : "+f"(acc[mi][nj][0]), "+f"(acc[mi][nj][1]),
                          "+f"(acc[mi][nj][2]), "+f"(acc[mi][nj][3])
                        : "r"(a[mi][0]), "r"(a[mi][1]), "r"(a[mi][2]), "r"(a[mi][3]),
                          "r"(b0), "r"(b1));
                }
        }
        __syncthreads();
    }

    // ---- epilogue: LN-folded affine + relu + fp16 store + row partial sums ----
    float* sm = (float*)smem;   // reuse pipeline smem (all warps past last sync)
#pragma unroll
    for (int mi = 0; mi < 4; mi++) {
#pragma unroll
        for (int h = 0; h < 2; h++) {
            const int r_local = warpM * 64 + mi * 16 + (lane >> 2) + h * 8;
            const int grow = m0 + r_local;
            float r = 1.f, rm = 0.f;
            if (fused) { const float2 st = __ldg(&stats[grow]); r = st.x; rm = st.y; }
            float s = 0.f, sq = 0.f;
#pragma unroll
            for (int nj = 0; nj < 4; nj++) {
                const int col = n0 + warpN * 32 + nj * 8 + (lane & 3) * 2;
                float c1a = 0.f, c1b = 0.f;
                if (fused) { c1a = __ldg(c1 + col); c1b = __ldg(c1 + col + 1); }
                const float c2a = __ldg(c2 + col), c2b = __ldg(c2 + col + 1);
                const float v0 = fmaxf(fmaf(r, acc[mi][nj][h * 2 + 0], fmaf(rm, c1a, c2a)), 0.f);
                const float v1 = fmaxf(fmaf(r, acc[mi][nj][h * 2 + 1], fmaf(rm, c1b, c2b)), 0.f);
                *(__half2*)(out16 + (size_t)grow * HDIM + col) = __floats2half2_rn(v0, v1);
                s += v0 + v1;
                sq += v0 * v0 + v1 * v1;
            }
            s  += __shfl_xor_sync(0xFFFFFFFFu, s, 1);
            s  += __shfl_xor_sync(0xFFFFFFFFu, s, 2);
            sq += __shfl_xor_sync(0xFFFFFFFFu, sq, 1);
            sq += __shfl_xor_sync(0xFFFFFFFFu, sq, 2);
            if ((lane & 3) == 0) {
                sm[(warpN * 128 + r_local) * 2 + 0] = s;
                sm[(warpN * 128 + r_local) * 2 + 1] = sq;
            }
        }
    }
    __syncthreads();
    if (tid < 128) {
        float s = 0.f, sq = 0.f;
#pragma unroll
        for (int w = 0; w < 4; w++) {
            s  += sm[(w * 128 + tid) * 2 + 0];
            sq += sm[(w * 128 + tid) * 2 + 1];
        }
        part[(size_t)(m0 + tid) * 8 + blockIdx.x] = make_float2(s, sq);
    }
}

// ---------------- per-layer weight prep: W' = gamma⊙W (fp16), c1, c2 ----------------
__global__ void wprep(const float* __restrict__ w, const float* __restrict__ gamma,
                      const float* __restrict__ beta, const float* __restrict__ bias)
{
    __shared__ float r1[4], r2[4];
    const int n = blockIdx.x;            // 0 .. L*H-1
    const int l = n >> 10, nl = n & 1023;
    const int tid = threadIdx.x;
    const float* wr = w + (size_t)n * HDIM;
    const float* g = gamma + l * HDIM;
    const float* bt = beta + l * HDIM;
    float s1 = 0.f, s2 = 0.f;
    for (int k = tid; k < HDIM; k += 128) {
        const float wv = wr[k], gv = g[k];
        g_w16[(size_t)n * HDIM + k] = __float2half_rn(gv * wv);
        s1 += gv * wv;
        s2 += bt[k] * wv;
    }
#pragma unroll
    for (int o = 16; o > 0; o >>= 1) {
        s1 += __shfl_xor_sync(0xFFFFFFFFu, s1, o);
        s2 += __shfl_xor_sync(0xFFFFFFFFu, s2, o);
    }
    const int wi = tid >> 5;
    if ((tid & 31) == 0) { r1[wi] = s1; r2[wi] = s2; }
    __syncthreads();
    if (tid == 0) {
        g_c1[n] = r1[0] + r1[1] + r1[2] + r1[3];
        g_c2[n] = r2[0] + r2[1] + r2[2] + r2[3] + bias[l * HDIM + nl];
    }
}

__global__ void stem_wpad(const float* __restrict__ w)
{
    const int i = blockIdx.x * blockDim.x + threadIdx.x;
    if (i < HDIM * 32) {
        const int j = i >> 5, k = i & 31;
        g_wstem16[i] = __float2half_rn((k < FIN) ? w[j * FIN + k] : 0.f);
    }
}

// ---------------- stem LN(26) + pad to 32, fp16 out ----------------
__global__ void stem_prep(const float* __restrict__ x, const float* __restrict__ g,
                          const float* __restrict__ bt)
{
    const int warp = (blockIdx.x * blockDim.x + threadIdx.x) >> 5;
    const int lane = threadIdx.x & 31;
    float v = (lane < FIN) ? x[(size_t)warp * FIN + lane] : 0.f;
    float s = v, sq = v * v;
#pragma unroll
    for (int o = 16; o > 0; o >>= 1) {
        s += __shfl_xor_sync(0xFFFFFFFFu, s, o);
        sq += __shfl_xor_sync(0xFFFFFFFFu, sq, o);
    }
    const float mean = s / (float)FIN;
    const float rstd = rsqrtf(sq / (float)FIN - mean * mean + EPSV);
    float ov = 0.f;
    if (lane < FIN) ov = (v - mean) * rstd * g[lane] + bt[lane];
    g_xpad16[(size_t)warp * 32 + lane] = __float2half_rn(ov);
}

// ---------------- combine per-row partials -> (rstd, -rstd*mean) ----------------
__global__ void stats_combine()
{
    const int row = blockIdx.x * 256 + threadIdx.x;
    const float2* p = g_part + (size_t)row * 8;
    float s = 0.f, sq = 0.f;
#pragma unroll
    for (int i = 0; i < 8; i++) { const float2 v = p[i]; s += v.x; sq += v.y; }
    const float mean = s * (1.f / HDIM);
    const float var = sq * (1.f / HDIM) - mean * mean;
    const float r = rsqrtf(var + EPSV);
    g_stats[row] = make_float2(r, -r * mean);
}

// ---------------- head: sigmoid(LN(h) @ w^T + b), stats precomputed ----------------
__global__ void head16(const float* __restrict__ g, const float* __restrict__ bb,
                       const float* __restrict__ w, const float* __restrict__ b1,
                       const __half* __restrict__ act, float* __restrict__ out)
{
    __shared__ float red[8];
    const int tid = threadIdx.x;
    const int row = blockIdx.x;
    const float2 st = g_stats[row];
    const __half2* hrow = (const __half2*)(act + (size_t)row * HDIM);
    const int c = tid * 4;
    const __half2 h01 = hrow[tid * 2], h23 = hrow[tid * 2 + 1];
    const float4 gg = *(const float4*)(g + c);
    const float4 bv = *(const float4*)(bb + c);
    const float4 wv = *(const float4*)(w + c);
    const float h0 = __low2float(h01), h1 = __high2float(h01);
    const float h2 = __low2float(h23), h3 = __high2float(h23);
    float d = ((h0 * st.x + st.y) * gg.x + bv.x) * wv.x +
              ((h1 * st.x + st.y) * gg.y + bv.y) * wv.y +
              ((h2 * st.x + st.y) * gg.z + bv.z) * wv.z +
              ((h3 * st.x + st.y) * gg.w + bv.w) * wv.w;
#pragma unroll
    for (int o = 16; o > 0; o >>= 1)
        d += __shfl_xor_sync(0xFFFFFFFFu, d, o);
    const int wI = tid >> 5, l = tid & 31;
    if (l == 0) red[wI] = d;
    __syncthreads();
    if (tid == 0) {
        const float a = red[0] + red[1] + red[2] + red[3] + red[4] + red[5] + red[6] + red[7];
        out[row] = 1.f / (1.f + expf(-(a + b1[0])));
    }
}

extern "C" void kernel_launch(void* const* d_in, const int* in_sizes, int n_in,
                              void* d_out, int out_size)
{
    const float* x          = (const float*)d_in[0];
    const float* st_gamma   = (const float*)d_in[1];
    const float* st_beta    = (const float*)d_in[2];
    const float* st_w       = (const float*)d_in[3];
    const float* st_b       = (const float*)d_in[4];
    const float* blk_gamma  = (const float*)d_in[5];
    const float* blk_beta   = (const float*)d_in[6];
    const float* blk_w      = (const float*)d_in[7];
    const float* blk_b      = (const float*)d_in[8];
    const float* last_gamma = (const float*)d_in[9];
    const float* last_beta  = (const float*)d_in[10];
    const float* last_w     = (const float*)d_in[11];
    const float* last_b     = (const float*)d_in[12];
    float* out = (float*)d_out;

    static bool attr_done = false;
    if (!attr_done) {
        cudaFuncSetAttribute(gemm16, cudaFuncAttributeMaxDynamicSharedMemorySize, GEMM_SMEM);
        attr_done = true;
    }

    __half* a0;    cudaGetSymbolAddress((void**)&a0, g_a0);
    __half* a1;    cudaGetSymbolAddress((void**)&a1, g_a1);
    __half* xpad;  cudaGetSymbolAddress((void**)&xpad, g_xpad16);
    __half* w16;   cudaGetSymbolAddress((void**)&w16, g_w16);
    __half* wstem; cudaGetSymbolAddress((void**)&wstem, g_wstem16);
    float2* part;  cudaGetSymbolAddress((void**)&part, g_part);
    float2* stats; cudaGetSymbolAddress((void**)&stats, g_stats);
    float* c1;     cudaGetSymbolAddress((void**)&c1, g_c1);
    float* c2;     cudaGetSymbolAddress((void**)&c2, g_c2);

    wprep<<<NLAYERS * HDIM, 128>>>(blk_w, blk_gamma, blk_beta, blk_b);
    stem_wpad<<<(HDIM * 32) / 256, 256>>>(st_w);
    stem_prep<<<B_ROWS / 8, 256>>>(x, st_gamma, st_beta);

    // stem GEMM: plain epilogue (fused=0), c2 = st_b
    gemm16<<<dim3(HDIM / 128, B_ROWS / 128), 256, GEMM_SMEM>>>(
        xpad, 32, wstem, 32, nullptr, nullptr, st_b, a0, part, 1, 0);
    stats_combine<<<B_ROWS / 256, 256>>>();

    __half* bufs[2] = { a0, a1 };
    for (int l = 0; l < NLAYERS; l++) {
        gemm16<<<dim3(HDIM / 128, B_ROWS / 128), 256, GEMM_SMEM>>>(
            bufs[l & 1], HDIM, w16 + (size_t)l * HDIM * HDIM, HDIM,
            stats, c1 + l * HDIM, c2 + l * HDIM,
            bufs[(l & 1) ^ 1], part, HDIM / 32, 1);
        stats_combine<<<B_ROWS / 256, 256>>>();
    }

    head16<<<B_ROWS, 256>>>(last_gamma, last_beta, last_w, last_b, a0, out);
}

// round 9
// speedup vs baseline: 2.4578x; 1.1855x over previous
#include <cuda_runtime.h>
#include <cuda_fp16.h>
#include <cstdint>

#define B_ROWS 65536
#define HDIM 1024
#define NLAYERS 8
#define FIN 26
#define EPSV 1e-5f

__device__ __half g_a0[(size_t)B_ROWS * HDIM];
__device__ __half g_a1[(size_t)B_ROWS * HDIM];
__device__ __half g_xpad16[(size_t)B_ROWS * 64];
__device__ __half g_w16[(size_t)NLAYERS * HDIM * HDIM];   // gamma ⊙ W, fp16
__device__ __half g_wstem16[HDIM * 64];
__device__ float2 g_part0[(size_t)B_ROWS * 8];
__device__ float2 g_part1[(size_t)B_ROWS * 8];
__device__ float  g_c1[NLAYERS * HDIM];
__device__ float  g_c2[NLAYERS * HDIM];

__device__ __forceinline__ uint32_t smem_u32(const void* p) {
    uint32_t a;
    asm("{ .reg .u64 t; cvta.to.shared.u64 t, %1; cvt.u32.u64 %0, t; }" : "=r"(a) : "l"(p));
    return a;
}

// ---------------- fp16 mma.sync GEMM, fused LN epilogue + fused stats ----------------
// CTA tile 128x128, warps 2(M)x4(N), warp tile 64x32. K-chunk 64, 3 stages.
// SMEM row stride 72 halves (144B): 8-row ldmatrix conflict-free.
#define KC 64
#define KP 72
#define STAGES 3
#define STAGE_B ((128 + 128) * KP * 2)     // 36864 bytes
#define GEMM_SMEM (STAGES * STAGE_B)       // 110592

__global__ void __launch_bounds__(256, 2) gemm16(
    const __half* __restrict__ A, int lda,
    const __half* __restrict__ W, int ldw,
    const float2* __restrict__ part_in,
    const float* __restrict__ c1, const float* __restrict__ c2,
    __half* __restrict__ out16, float2* __restrict__ part_out,
    int nk, int fused)
{
    extern __shared__ __half smem[];
    const int tid = threadIdx.x;
    const int wid = tid >> 5, lane = tid & 31;
    const int warpM = wid & 1, warpN = wid >> 1;
    const int m0 = blockIdx.y * 128, n0 = blockIdx.x * 128;
    const uint32_t base = smem_u32(smem);

    auto load_stage = [&](int ki, int s) {
        const uint32_t st = base + (uint32_t)s * STAGE_B;
#pragma unroll
        for (int i = 0; i < 4; i++) {       // A: 128 rows x 128B
            const int seg = tid + i * 256;
            const int row = seg >> 3, c = seg & 7;
            const __half* src = A + (size_t)(m0 + row) * lda + ki * KC + c * 8;
            asm volatile("cp.async.cg.shared.global [%0], [%1], 16;"
                         :: "r"(st + row * 144 + c * 16), "l"(src));
        }
#pragma unroll
        for (int i = 0; i < 4; i++) {       // B: 128 rows x 128B
            const int seg = tid + i * 256;
            const int row = seg >> 3, c = seg & 7;
            const __half* src = W + (size_t)(n0 + row) * ldw + ki * KC + c * 8;
            asm volatile("cp.async.cg.shared.global [%0], [%1], 16;"
                         :: "r"(st + 128 * 144 + row * 144 + c * 16), "l"(src));
        }
        asm volatile("cp.async.commit_group;" ::: "memory");
    };

    const int aRow = warpM * 64 + (lane & 7) + ((lane >> 3) & 1) * 8;
    const int aK   = (lane >> 4) * 8;
    const int bN   = warpN * 32 + (lane & 7) + (lane >> 4) * 8;
    const int bK   = ((lane >> 3) & 1) * 8;

    float acc[4][4][4];
#pragma unroll
    for (int mi = 0; mi < 4; mi++)
#pragma unroll
        for (int nj = 0; nj < 4; nj++)
#pragma unroll
            for (int q = 0; q < 4; q++) acc[mi][nj][q] = 0.f;

#pragma unroll
    for (int p = 0; p < STAGES - 1; p++)
        if (p < nk) load_stage(p, p);

    int sidx = 0;
    for (int ki = 0; ki < nk; ki++) {
        if (ki + 1 < nk) asm volatile("cp.async.wait_group 1;" ::: "memory");
        else             asm volatile("cp.async.wait_group 0;" ::: "memory");
        __syncthreads();
        if (ki + STAGES - 1 < nk) {
            int ns = sidx + STAGES - 1;
            if (ns >= STAGES) ns -= STAGES;
            load_stage(ki + STAGES - 1, ns);
        }

        const uint32_t As = base + (uint32_t)sidx * STAGE_B;
        const uint32_t Bs = As + 128 * 144;
#pragma unroll
        for (int k0 = 0; k0 < KC; k0 += 16) {
            uint32_t a[4][4], b[2][4];
#pragma unroll
            for (int mi = 0; mi < 4; mi++) {
                const uint32_t ad = As + (uint32_t)((aRow + mi * 16) * KP + k0 + aK) * 2;
                asm volatile("ldmatrix.sync.aligned.m8n8.x4.shared.b16 {%0,%1,%2,%3}, [%4];"
                             : "=r"(a[mi][0]), "=r"(a[mi][1]), "=r"(a[mi][2]), "=r"(a[mi][3])
                             : "r"(ad));
            }
#pragma unroll
            for (int p = 0; p < 2; p++) {
                const uint32_t bd = Bs + (uint32_t)((bN + p * 16) * KP + k0 + bK) * 2;
                asm volatile("ldmatrix.sync.aligned.m8n8.x4.shared.b16 {%0,%1,%2,%3}, [%4];"
                             : "=r"(b[p][0]), "=r"(b[p][1]), "=r"(b[p][2]), "=r"(b[p][3])
                             : "r"(bd));
            }
#pragma unroll
            for (int mi = 0; mi < 4; mi++)
#pragma unroll
                for (int nj = 0; nj < 4; nj++) {
                    const uint32_t b0 = b[nj >> 1][(nj & 1) * 2];
                    const uint32_t b1 = b[nj >> 1][(nj & 1) * 2 + 1];
                    asm volatile(
                        "mma.sync.aligned.m16n8k16.row.col.f32.f16.f16.f32 "
                        "{%0,%1,%2,%3}, {%4,%5,%6,%7}, {%8,%9}, {%0,%1,%2,%3};"
                        : "+f"(acc[mi][nj][0]), "+f"(acc[mi][nj][1]),
                          "+f"(acc[mi][nj][2]), "+f"(acc[mi][nj][3])
                        : "r"(a[mi][0]), "r"(a[mi][1]), "r"(a[mi][2]), "r"(a[mi][3]),
                          "r"(b0), "r"(b1));
                }
        }
        if (++sidx == STAGES) sidx = 0;
    }

    // ---- epilogue ----
    __syncthreads();                 // protect smem reuse
    float* sm = (float*)smem;        // [0..255]: per-row (r, rm); [256..]: partials
    float* pm = sm + 256;
    if (fused) {
        if (tid < 128) {
            const float2* p = part_in + (size_t)(m0 + tid) * 8;
            float s = 0.f, sq = 0.f;
#pragma unroll
            for (int i = 0; i < 8; i++) { const float2 v = p[i]; s += v.x; sq += v.y; }
            const float mean = s * (1.f / HDIM);
            const float var = sq * (1.f / HDIM) - mean * mean;
            const float r = rsqrtf(var + EPSV);
            sm[tid * 2] = r;
            sm[tid * 2 + 1] = -r * mean;
        }
        __syncthreads();
    }

#pragma unroll
    for (int mi = 0; mi < 4; mi++) {
#pragma unroll
        for (int h = 0; h < 2; h++) {
            const int r_local = warpM * 64 + mi * 16 + (lane >> 2) + h * 8;
            const int grow = m0 + r_local;
            float r = 1.f, rm = 0.f;
            if (fused) { r = sm[r_local * 2]; rm = sm[r_local * 2 + 1]; }
            float s = 0.f, sq = 0.f;
#pragma unroll
            for (int nj = 0; nj < 4; nj++) {
                const int col = n0 + warpN * 32 + nj * 8 + (lane & 3) * 2;
                float c1a = 0.f, c1b = 0.f;
                if (fused) { c1a = __ldg(c1 + col); c1b = __ldg(c1 + col + 1); }
                const float c2a = __ldg(c2 + col), c2b = __ldg(c2 + col + 1);
                const float v0 = fmaxf(fmaf(r, acc[mi][nj][h * 2 + 0], fmaf(rm, c1a, c2a)), 0.f);
                const float v1 = fmaxf(fmaf(r, acc[mi][nj][h * 2 + 1], fmaf(rm, c1b, c2b)), 0.f);
                *(__half2*)(out16 + (size_t)grow * HDIM + col) = __floats2half2_rn(v0, v1);
                s += v0 + v1;
                sq += v0 * v0 + v1 * v1;
            }
            s  += __shfl_xor_sync(0xFFFFFFFFu, s, 1);
            s  += __shfl_xor_sync(0xFFFFFFFFu, s, 2);
            sq += __shfl_xor_sync(0xFFFFFFFFu, sq, 1);
            sq += __shfl_xor_sync(0xFFFFFFFFu, sq, 2);
            if ((lane & 3) == 0) {
                pm[(warpN * 128 + r_local) * 2 + 0] = s;
                pm[(warpN * 128 + r_local) * 2 + 1] = sq;
            }
        }
    }
    __syncthreads();
    if (tid < 128) {
        float s = 0.f, sq = 0.f;
#pragma unroll
        for (int w = 0; w < 4; w++) {
            s  += pm[(w * 128 + tid) * 2 + 0];
            sq += pm[(w * 128 + tid) * 2 + 1];
        }
        part_out[(size_t)(m0 + tid) * 8 + blockIdx.x] = make_float2(s, sq);
    }
}

// ---------------- per-layer weight prep: W' = gamma⊙W (fp16), c1, c2 ----------------
__global__ void wprep(const float* __restrict__ w, const float* __restrict__ gamma,
                      const float* __restrict__ beta, const float* __restrict__ bias)
{
    __shared__ float r1[4], r2[4];
    const int n = blockIdx.x;
    const int l = n >> 10, nl = n & 1023;
    const int tid = threadIdx.x;
    const float* wr = w + (size_t)n * HDIM;
    const float* g = gamma + l * HDIM;
    const float* bt = beta + l * HDIM;
    float s1 = 0.f, s2 = 0.f;
    for (int k = tid; k < HDIM; k += 128) {
        const float wv = wr[k], gv = g[k];
        g_w16[(size_t)n * HDIM + k] = __float2half_rn(gv * wv);
        s1 += gv * wv;
        s2 += bt[k] * wv;
    }
#pragma unroll
    for (int o = 16; o > 0; o >>= 1) {
        s1 += __shfl_xor_sync(0xFFFFFFFFu, s1, o);
        s2 += __shfl_xor_sync(0xFFFFFFFFu, s2, o);
    }
    const int wi = tid >> 5;
    if ((tid & 31) == 0) { r1[wi] = s1; r2[wi] = s2; }
    __syncthreads();
    if (tid == 0) {
        g_c1[n] = r1[0] + r1[1] + r1[2] + r1[3];
        g_c2[n] = r2[0] + r2[1] + r2[2] + r2[3] + bias[l * HDIM + nl];
    }
}

__global__ void stem_wpad(const float* __restrict__ w)
{
    const int i = blockIdx.x * blockDim.x + threadIdx.x;
    if (i < HDIM * 64) {
        const int j = i >> 6, k = i & 63;
        g_wstem16[i] = __float2half_rn((k < FIN) ? w[j * FIN + k] : 0.f);
    }
}

// ---------------- stem LN(26) + pad to 64, fp16 out ----------------
__global__ void stem_prep(const float* __restrict__ x, const float* __restrict__ g,
                          const float* __restrict__ bt)
{
    const int warp = (blockIdx.x * blockDim.x + threadIdx.x) >> 5;
    const int lane = threadIdx.x & 31;
    float v = (lane < FIN) ? x[(size_t)warp * FIN + lane] : 0.f;
    float s = v, sq = v * v;
#pragma unroll
    for (int o = 16; o > 0; o >>= 1) {
        s += __shfl_xor_sync(0xFFFFFFFFu, s, o);
        sq += __shfl_xor_sync(0xFFFFFFFFu, sq, o);
    }
    const float mean = s / (float)FIN;
    const float rstd = rsqrtf(sq / (float)FIN - mean * mean + EPSV);
    float ov = 0.f;
    if (lane < FIN) ov = (v - mean) * rstd * g[lane] + bt[lane];
    g_xpad16[(size_t)warp * 64 + lane] = __float2half_rn(ov);
    g_xpad16[(size_t)warp * 64 + 32 + lane] = __half(0.f);
}

// ---------------- head: stats from partials, sigmoid(LN(h) @ w^T + b) ----------------
__global__ void head16(const float* __restrict__ g, const float* __restrict__ bb,
                       const float* __restrict__ w, const float* __restrict__ b1,
                       const __half* __restrict__ act, const float2* __restrict__ part,
                       float* __restrict__ out)
{
    __shared__ float red[8];
    __shared__ float2 stat;
    const int tid = threadIdx.x;
    const int row = blockIdx.x;
    if (tid == 0) {
        const float2* p = part + (size_t)row * 8;
        float s = 0.f, sq = 0.f;
#pragma unroll
        for (int i = 0; i < 8; i++) { const float2 v = p[i]; s += v.x; sq += v.y; }
        const float mean = s * (1.f / HDIM);
        const float r = rsqrtf(sq * (1.f / HDIM) - mean * mean + EPSV);
        stat = make_float2(r, -r * mean);
    }
    __syncthreads();
    const float2 st = stat;
    const __half2* hrow = (const __half2*)(act + (size_t)row * HDIM);
    const int c = tid * 4;
    const __half2 h01 = hrow[tid * 2], h23 = hrow[tid * 2 + 1];
    const float4 gg = *(const float4*)(g + c);
    const float4 bv = *(const float4*)(bb + c);
    const float4 wv = *(const float4*)(w + c);
    const float h0 = __low2float(h01), h1 = __high2float(h01);
    const float h2 = __low2float(h23), h3 = __high2float(h23);
    float d = ((h0 * st.x + st.y) * gg.x + bv.x) * wv.x +
              ((h1 * st.x + st.y) * gg.y + bv.y) * wv.y +
              ((h2 * st.x + st.y) * gg.z + bv.z) * wv.z +
              ((h3 * st.x + st.y) * gg.w + bv.w) * wv.w;
#pragma unroll
    for (int o = 16; o > 0; o >>= 1)
        d += __shfl_xor_sync(0xFFFFFFFFu, d, o);
    const int wI = tid >> 5, l = tid & 31;
    if (l == 0) red[wI] = d;
    __syncthreads();
    if (tid == 0) {
        const float a = red[0] + red[1] + red[2] + red[3] + red[4] + red[5] + red[6] + red[7];
        out[row] = 1.f / (1.f + expf(-(a + b1[0])));
    }
}

extern "C" void kernel_launch(void* const* d_in, const int* in_sizes, int n_in,
                              void* d_out, int out_size)
{
    const float* x          = (const float*)d_in[0];
    const float* st_gamma   = (const float*)d_in[1];
    const float* st_beta    = (const float*)d_in[2];
    const float* st_w       = (const float*)d_in[3];
    const float* st_b       = (const float*)d_in[4];
    const float* blk_gamma  = (const float*)d_in[5];
    const float* blk_beta   = (const float*)d_in[6];
    const float* blk_w      = (const float*)d_in[7];
    const float* blk_b      = (const float*)d_in[8];
    const float* last_gamma = (const float*)d_in[9];
    const float* last_beta  = (const float*)d_in[10];
    const float* last_w     = (const float*)d_in[11];
    const float* last_b     = (const float*)d_in[12];
    float* out = (float*)d_out;

    static bool attr_done = false;
    if (!attr_done) {
        cudaFuncSetAttribute(gemm16, cudaFuncAttributeMaxDynamicSharedMemorySize, GEMM_SMEM);
        attr_done = true;
    }

    __half* a0;    cudaGetSymbolAddress((void**)&a0, g_a0);
    __half* a1;    cudaGetSymbolAddress((void**)&a1, g_a1);
    __half* xpad;  cudaGetSymbolAddress((void**)&xpad, g_xpad16);
    __half* w16;   cudaGetSymbolAddress((void**)&w16, g_w16);
    __half* wstem; cudaGetSymbolAddress((void**)&wstem, g_wstem16);
    float2* part0; cudaGetSymbolAddress((void**)&part0, g_part0);
    float2* part1; cudaGetSymbolAddress((void**)&part1, g_part1);
    float* c1;     cudaGetSymbolAddress((void**)&c1, g_c1);
    float* c2;     cudaGetSymbolAddress((void**)&c2, g_c2);

    wprep<<<NLAYERS * HDIM, 128>>>(blk_w, blk_gamma, blk_beta, blk_b);
    stem_wpad<<<(HDIM * 64) / 256, 256>>>(st_w);
    stem_prep<<<B_ROWS / 8, 256>>>(x, st_gamma, st_beta);

    // stem: K=64 (1 chunk), plain epilogue (fused=0), writes part0
    gemm16<<<dim3(HDIM / 128, B_ROWS / 128), 256, GEMM_SMEM>>>(
        xpad, 64, wstem, 64, nullptr, nullptr, st_b, a0, part0, 1, 0);

    __half* abuf[2] = { a0, a1 };
    float2* pbuf[2] = { part0, part1 };
    for (int l = 0; l < NLAYERS; l++) {
        gemm16<<<dim3(HDIM / 128, B_ROWS / 128), 256, GEMM_SMEM>>>(
            abuf[l & 1], HDIM, w16 + (size_t)l * HDIM * HDIM, HDIM,
            pbuf[l & 1], c1 + l * HDIM, c2 + l * HDIM,
            abuf[(l & 1) ^ 1], pbuf[(l & 1) ^ 1], HDIM / KC, 1);
    }

    head16<<<B_ROWS, 256>>>(last_gamma, last_beta, last_w, last_b, a0, part0, out);
}

// round 11
// speedup vs baseline: 2.5466x; 1.0361x over previous
#include <cuda_runtime.h>
#include <cuda_fp16.h>
#include <cstdint>

#define B_ROWS 65536
#define HDIM 1024
#define NLAYERS 8
#define FIN 26
#define EPSV 1e-5f

__device__ __half g_a0[(size_t)B_ROWS * HDIM];
__device__ __half g_a1[(size_t)B_ROWS * HDIM];
__device__ __half g_xpad16[(size_t)B_ROWS * 64];
__device__ __half g_w16[(size_t)NLAYERS * HDIM * HDIM];   // gamma ⊙ W, fp16
__device__ __half g_wstem16[HDIM * 64];
__device__ float2 g_part0[(size_t)B_ROWS * 8];
__device__ float2 g_part1[(size_t)B_ROWS * 8];
__device__ float  g_c1[NLAYERS * HDIM];
__device__ float  g_c2[NLAYERS * HDIM];

__device__ __forceinline__ uint32_t smem_u32(const void* p) {
    uint32_t a;
    asm("{ .reg .u64 t; cvta.to.shared.u64 t, %1; cvt.u32.u64 %0, t; }" : "=r"(a) : "l"(p));
    return a;
}

// ---------------- fp16 mma.sync GEMM, fused LN epilogue + fused stats ----------------
// CTA tile 64x128, 128 thr, warps 2(M)x2(N), warp tile 32x64. K-chunk 64, 2 stages.
// 4 CTAs/SM. Double-buffer discipline: wait_group 0 -> barrier -> issue next load.
#define KC 64
#define KP 72
#define TM 64
#define STAGE_B ((TM + 128) * KP * 2)      // 27648 bytes
#define GEMM_SMEM (2 * STAGE_B)            // 55296

__global__ void __launch_bounds__(128, 4) gemm16(
    const __half* __restrict__ A, int lda,
    const __half* __restrict__ W, int ldw,
    const float2* __restrict__ part_in,
    const float* __restrict__ c1, const float* __restrict__ c2,
    __half* __restrict__ out16, float2* __restrict__ part_out,
    int nk, int fused)
{
    extern __shared__ __half smem[];
    const int tid = threadIdx.x;
    const int wid = tid >> 5, lane = tid & 31;
    const int warpM = wid & 1, warpN = wid >> 1;
    const int m0 = blockIdx.y * TM, n0 = blockIdx.x * 128;
    const uint32_t base = smem_u32(smem);

    auto load_stage = [&](int ki, int s) {
        const uint32_t st = base + (uint32_t)s * STAGE_B;
#pragma unroll
        for (int i = 0; i < 4; i++) {       // A: 64 rows x 128B
            const int seg = tid + i * 128;
            const int row = seg >> 3, c = seg & 7;
            const __half* src = A + (size_t)(m0 + row) * lda + ki * KC + c * 8;
            asm volatile("cp.async.cg.shared.global [%0], [%1], 16;"
                         :: "r"(st + row * 144 + c * 16), "l"(src));
        }
#pragma unroll
        for (int i = 0; i < 8; i++) {       // B: 128 rows x 128B
            const int seg = tid + i * 128;
            const int row = seg >> 3, c = seg & 7;
            const __half* src = W + (size_t)(n0 + row) * ldw + ki * KC + c * 8;
            asm volatile("cp.async.cg.shared.global [%0], [%1], 16;"
                         :: "r"(st + TM * 144 + row * 144 + c * 16), "l"(src));
        }
        asm volatile("cp.async.commit_group;" ::: "memory");
    };

    const int aRow = warpM * 32 + (lane & 7) + ((lane >> 3) & 1) * 8;
    const int aK   = (lane >> 4) * 8;
    const int bN   = warpN * 64 + (lane & 7) + (lane >> 4) * 8;
    const int bK   = ((lane >> 3) & 1) * 8;

    float acc[2][8][4];
#pragma unroll
    for (int mi = 0; mi < 2; mi++)
#pragma unroll
        for (int nj = 0; nj < 8; nj++)
#pragma unroll
            for (int q = 0; q < 4; q++) acc[mi][nj][q] = 0.f;

    load_stage(0, 0);

    for (int ki = 0; ki < nk; ki++) {
        const int s = ki & 1;
        asm volatile("cp.async.wait_group 0;" ::: "memory");  // stage s fully loaded
        __syncthreads();   // all warps done with stage s^1 from iter ki-1
        if (ki + 1 < nk) load_stage(ki + 1, s ^ 1);           // overlaps mma below

        const uint32_t As = base + (uint32_t)s * STAGE_B;
        const uint32_t Bs = As + TM * 144;
#pragma unroll
        for (int k0 = 0; k0 < KC; k0 += 16) {
            uint32_t a[2][4], b[4][4];
#pragma unroll
            for (int mi = 0; mi < 2; mi++) {
                const uint32_t ad = As + (uint32_t)((aRow + mi * 16) * KP + k0 + aK) * 2;
                asm volatile("ldmatrix.sync.aligned.m8n8.x4.shared.b16 {%0,%1,%2,%3}, [%4];"
                             : "=r"(a[mi][0]), "=r"(a[mi][1]), "=r"(a[mi][2]), "=r"(a[mi][3])
                             : "r"(ad));
            }
#pragma unroll
            for (int p = 0; p < 4; p++) {
                const uint32_t bd = Bs + (uint32_t)((bN + p * 16) * KP + k0 + bK) * 2;
                asm volatile("ldmatrix.sync.aligned.m8n8.x4.shared.b16 {%0,%1,%2,%3}, [%4];"
                             : "=r"(b[p][0]), "=r"(b[p][1]), "=r"(b[p][2]), "=r"(b[p][3])
                             : "r"(bd));
            }
#pragma unroll
            for (int mi = 0; mi < 2; mi++)
#pragma unroll
                for (int nj = 0; nj < 8; nj++) {
                    const uint32_t b0 = b[nj >> 1][(nj & 1) * 2];
                    const uint32_t b1 = b[nj >> 1][(nj & 1) * 2 + 1];
                    asm volatile(
                        "mma.sync.aligned.m16n8k16.row.col.f32.f16.f16.f32 "
                        "{%0,%1,%2,%3}, {%4,%5,%6,%7}, {%8,%9}, {%0,%1,%2,%3};"
                        : "+f"(acc[mi][nj][0]), "+f"(acc[mi][nj][1]),
                          "+f"(acc[mi][nj][2]), "+f"(acc[mi][nj][3])
                        : "r"(a[mi][0]), "r"(a[mi][1]), "r"(a[mi][2]), "r"(a[mi][3]),
                          "r"(b0), "r"(b1));
                }
        }
    }

    // ---- epilogue ----
    __syncthreads();
    float* sm = (float*)smem;        // [0..127]: per-row (r, rm); [128..]: partials
    float* pm = sm + 128;
    if (fused) {
        if (tid < TM) {
            const float2* p = part_in + (size_t)(m0 + tid) * 8;
            float s = 0.f, sq = 0.f;
#pragma unroll
            for (int i = 0; i < 8; i++) { const float2 v = p[i]; s += v.x; sq += v.y; }
            const float mean = s * (1.f / HDIM);
            const float var = sq * (1.f / HDIM) - mean * mean;
            const float r = rsqrtf(var + EPSV);
            sm[tid * 2] = r;
            sm[tid * 2 + 1] = -r * mean;
        }
        __syncthreads();
    }

#pragma unroll
    for (int mi = 0; mi < 2; mi++) {
#pragma unroll
        for (int h = 0; h < 2; h++) {
            const int r_local = warpM * 32 + mi * 16 + (lane >> 2) + h * 8;
            const int grow = m0 + r_local;
            float r = 1.f, rm = 0.f;
            if (fused) { r = sm[r_local * 2]; rm = sm[r_local * 2 + 1]; }
            float s = 0.f, sq = 0.f;
#pragma unroll
            for (int nj = 0; nj < 8; nj++) {
                const int col = n0 + warpN * 64 + nj * 8 + (lane & 3) * 2;
                float c1a = 0.f, c1b = 0.f;
                if (fused) { c1a = __ldg(c1 + col); c1b = __ldg(c1 + col + 1); }
                const float c2a = __ldg(c2 + col), c2b = __ldg(c2 + col + 1);
                const float v0 = fmaxf(fmaf(r, acc[mi][nj][h * 2 + 0], fmaf(rm, c1a, c2a)), 0.f);
                const float v1 = fmaxf(fmaf(r, acc[mi][nj][h * 2 + 1], fmaf(rm, c1b, c2b)), 0.f);
                *(__half2*)(out16 + (size_t)grow * HDIM + col) = __floats2half2_rn(v0, v1);
                s += v0 + v1;
                sq += v0 * v0 + v1 * v1;
            }
            s  += __shfl_xor_sync(0xFFFFFFFFu, s, 1);
            s  += __shfl_xor_sync(0xFFFFFFFFu, s, 2);
            sq += __shfl_xor_sync(0xFFFFFFFFu, sq, 1);
            sq += __shfl_xor_sync(0xFFFFFFFFu, sq, 2);
            if ((lane & 3) == 0) {
                pm[(warpN * TM + r_local) * 2 + 0] = s;
                pm[(warpN * TM + r_local) * 2 + 1] = sq;
            }
        }
    }
    __syncthreads();
    if (tid < TM) {
        float s = 0.f, sq = 0.f;
#pragma unroll
        for (int w = 0; w < 2; w++) {
            s  += pm[(w * TM + tid) * 2 + 0];
            sq += pm[(w * TM + tid) * 2 + 1];
        }
        part_out[(size_t)(m0 + tid) * 8 + blockIdx.x] = make_float2(s, sq);
    }
}

// ---------------- per-layer weight prep: W' = gamma⊙W (fp16), c1, c2 ----------------
__global__ void wprep(const float* __restrict__ w, const float* __restrict__ gamma,
                      const float* __restrict__ beta, const float* __restrict__ bias)
{
    __shared__ float r1[4], r2[4];
    const int n = blockIdx.x;
    const int l = n >> 10, nl = n & 1023;
    const int tid = threadIdx.x;
    const float* wr = w + (size_t)n * HDIM;
    const float* g = gamma + l * HDIM;
    const float* bt = beta + l * HDIM;
    float s1 = 0.f, s2 = 0.f;
    for (int k = tid; k < HDIM; k += 128) {
        const float wv = wr[k], gv = g[k];
        g_w16[(size_t)n * HDIM + k] = __float2half_rn(gv * wv);
        s1 += gv * wv;
        s2 += bt[k] * wv;
    }
#pragma unroll
    for (int o = 16; o > 0; o >>= 1) {
        s1 += __shfl_xor_sync(0xFFFFFFFFu, s1, o);
        s2 += __shfl_xor_sync(0xFFFFFFFFu, s2, o);
    }
    const int wi = tid >> 5;
    if ((tid & 31) == 0) { r1[wi] = s1; r2[wi] = s2; }
    __syncthreads();
    if (tid == 0) {
        g_c1[n] = r1[0] + r1[1] + r1[2] + r1[3];
        g_c2[n] = r2[0] + r2[1] + r2[2] + r2[3] + bias[l * HDIM + nl];
    }
}

__global__ void stem_wpad(const float* __restrict__ w)
{
    const int i = blockIdx.x * blockDim.x + threadIdx.x;
    if (i < HDIM * 64) {
        const int j = i >> 6, k = i & 63;
        g_wstem16[i] = __float2half_rn((k < FIN) ? w[j * FIN + k] : 0.f);
    }
}

// ---------------- stem LN(26) + pad to 64, fp16 out ----------------
__global__ void stem_prep(const float* __restrict__ x, const float* __restrict__ g,
                          const float* __restrict__ bt)
{
    const int warp = (blockIdx.x * blockDim.x + threadIdx.x) >> 5;
    const int lane = threadIdx.x & 31;
    float v = (lane < FIN) ? x[(size_t)warp * FIN + lane] : 0.f;
    float s = v, sq = v * v;
#pragma unroll
    for (int o = 16; o > 0; o >>= 1) {
        s += __shfl_xor_sync(0xFFFFFFFFu, s, o);
        sq += __shfl_xor_sync(0xFFFFFFFFu, sq, o);
    }
    const float mean = s / (float)FIN;
    const float rstd = rsqrtf(sq / (float)FIN - mean * mean + EPSV);
    float ov = 0.f;
    if (lane < FIN) ov = (v - mean) * rstd * g[lane] + bt[lane];
    g_xpad16[(size_t)warp * 64 + lane] = __float2half_rn(ov);
    g_xpad16[(size_t)warp * 64 + 32 + lane] = __half(0.f);
}

// ---------------- head: stats from partials, sigmoid(LN(h) @ w^T + b) ----------------
__global__ void head16(const float* __restrict__ g, const float* __restrict__ bb,
                       const float* __restrict__ w, const float* __restrict__ b1,
                       const __half* __restrict__ act, const float2* __restrict__ part,
                       float* __restrict__ out)
{
    __shared__ float red[8];
    __shared__ float2 stat;
    const int tid = threadIdx.x;
    const int row = blockIdx.x;
    if (tid == 0) {
        const float2* p = part + (size_t)row * 8;
        float s = 0.f, sq = 0.f;
#pragma unroll
        for (int i = 0; i < 8; i++) { const float2 v = p[i]; s += v.x; sq += v.y; }
        const float mean = s * (1.f / HDIM);
        const float r = rsqrtf(sq * (1.f / HDIM) - mean * mean + EPSV);
        stat = make_float2(r, -r * mean);
    }
    __syncthreads();
    const float2 st = stat;
    const __half2* hrow = (const __half2*)(act + (size_t)row * HDIM);
    const int c = tid * 4;
    const __half2 h01 = hrow[tid * 2], h23 = hrow[tid * 2 + 1];
    const float4 gg = *(const float4*)(g + c);
    const float4 bv = *(const float4*)(bb + c);
    const float4 wv = *(const float4*)(w + c);
    const float h0 = __low2float(h01), h1 = __high2float(h01);
    const float h2 = __low2float(h23), h3 = __high2float(h23);
    float d = ((h0 * st.x + st.y) * gg.x + bv.x) * wv.x +
              ((h1 * st.x + st.y) * gg.y + bv.y) * wv.y +
              ((h2 * st.x + st.y) * gg.z + bv.z) * wv.z +
              ((h3 * st.x + st.y) * gg.w + bv.w) * wv.w;
#pragma unroll
    for (int o = 16; o > 0; o >>= 1)
        d += __shfl_xor_sync(0xFFFFFFFFu, d, o);
    const int wI = tid >> 5, l = tid & 31;
    if (l == 0) red[wI] = d;
    __syncthreads();
    if (tid == 0) {
        const float a = red[0] + red[1] + red[2] + red[3] + red[4] + red[5] + red[6] + red[7];
        out[row] = 1.f / (1.f + expf(-(a + b1[0])));
    }
}

extern "C" void kernel_launch(void* const* d_in, const int* in_sizes, int n_in,
                              void* d_out, int out_size)
{
    const float* x          = (const float*)d_in[0];
    const float* st_gamma   = (const float*)d_in[1];
    const float* st_beta    = (const float*)d_in[2];
    const float* st_w       = (const float*)d_in[3];
    const float* st_b       = (const float*)d_in[4];
    const float* blk_gamma  = (const float*)d_in[5];
    const float* blk_beta   = (const float*)d_in[6];
    const float* blk_w      = (const float*)d_in[7];
    const float* blk_b      = (const float*)d_in[8];
    const float* last_gamma = (const float*)d_in[9];
    const float* last_beta  = (const float*)d_in[10];
    const float* last_w     = (const float*)d_in[11];
    const float* last_b     = (const float*)d_in[12];
    float* out = (float*)d_out;

    static bool attr_done = false;
    if (!attr_done) {
        cudaFuncSetAttribute(gemm16, cudaFuncAttributeMaxDynamicSharedMemorySize, GEMM_SMEM);
        attr_done = true;
    }

    __half* a0;    cudaGetSymbolAddress((void**)&a0, g_a0);
    __half* a1;    cudaGetSymbolAddress((void**)&a1, g_a1);
    __half* xpad;  cudaGetSymbolAddress((void**)&xpad, g_xpad16);
    __half* w16;   cudaGetSymbolAddress((void**)&w16, g_w16);
    __half* wstem; cudaGetSymbolAddress((void**)&wstem, g_wstem16);
    float2* part0; cudaGetSymbolAddress((void**)&part0, g_part0);
    float2* part1; cudaGetSymbolAddress((void**)&part1, g_part1);
    float* c1;     cudaGetSymbolAddress((void**)&c1, g_c1);
    float* c2;     cudaGetSymbolAddress((void**)&c2, g_c2);

    wprep<<<NLAYERS * HDIM, 128>>>(blk_w, blk_gamma, blk_beta, blk_b);
    stem_wpad<<<(HDIM * 64) / 256, 256>>>(st_w);
    stem_prep<<<B_ROWS / 8, 256>>>(x, st_gamma, st_beta);

    // stem: K=64 (1 chunk), plain epilogue (fused=0), writes part0
    gemm16<<<dim3(HDIM / 128, B_ROWS / TM), 128, GEMM_SMEM>>>(
        xpad, 64, wstem, 64, nullptr, nullptr, st_b, a0, part0, 1, 0);

    __half* abuf[2] = { a0, a1 };
    float2* pbuf[2] = { part0, part1 };
    for (int l = 0; l < NLAYERS; l++) {
        gemm16<<<dim3(HDIM / 128, B_ROWS / TM), 128, GEMM_SMEM>>>(
            abuf[l & 1], HDIM, w16 + (size_t)l * HDIM * HDIM, HDIM,
            pbuf[l & 1], c1 + l * HDIM, c2 + l * HDIM,
            abuf[(l & 1) ^ 1], pbuf[(l & 1) ^ 1], HDIM / KC, 1);
    }

    head16<<<B_ROWS, 256>>>(last_gamma, last_beta, last_w, last_b, a0, part0, out);
}